// round 5
// baseline (speedup 1.0000x reference)
#include <cuda_runtime.h>
#include <cuda_bf16.h>

#define BB 8
#define NN 64
#define DD 64
#define EE 32

// ---------------------------------------------------------------------------
// Scratch: W_e transposed + split into bf16 hi/lo, sector-interleaved.
// Per column (4096 of them), 128 bytes:
//   [kt=0: hi k0..15 (32B) | lo k0..15 (32B) | kt=1: hi k16..31 | lo k16..31]
// ---------------------------------------------------------------------------
__device__ __nv_bfloat16 g_W[DD * DD * EE * 2];   // 4096 cols x 64 bf16

__global__ void prep_w_kernel(const float* __restrict__ W_e)
{
    int idx = blockIdx.x * blockDim.x + threadIdx.x;   // over 32*4096
    if (idx >= EE * DD * DD) return;
    int k   = idx >> 12;          // 0..31
    int col = idx & 4095;
    float x = W_e[idx];
    __nv_bfloat16 h = __float2bfloat16(x);
    float lo = x - __bfloat162float(h);
    int kt = k >> 4, kk = k & 15;
    __nv_bfloat16* base = g_W + (size_t)col * 64 + kt * 32;
    base[kk]      = h;
    base[16 + kk] = __float2bfloat16(lo);
}

// ---------------------------------------------------------------------------
#define MMA_BF16(C, A, b0, b1)                                                 \
    asm volatile(                                                              \
        "mma.sync.aligned.m16n8k16.row.col.f32.bf16.bf16.f32 "                 \
        "{%0,%1,%2,%3}, {%4,%5,%6,%7}, {%8,%9}, {%0,%1,%2,%3};"                \
        : "+f"((C)[0]), "+f"((C)[1]), "+f"((C)[2]), "+f"((C)[3])               \
        : "r"((A)[0]), "r"((A)[1]), "r"((A)[2]), "r"((A)[3]),                  \
          "r"(b0), "r"(b1))

__device__ __forceinline__ void split2(float2 v, unsigned& h, unsigned& l)
{
    __nv_bfloat16 hx = __float2bfloat16(v.x);
    __nv_bfloat16 hy = __float2bfloat16(v.y);
    float lx = v.x - __bfloat162float(hx);
    float ly = v.y - __bfloat162float(hy);
    __nv_bfloat162 hh = __halves2bfloat162(hx, hy);
    __nv_bfloat162 ll = __halves2bfloat162(__float2bfloat16(lx),
                                           __float2bfloat16(ly));
    h = *reinterpret_cast<unsigned*>(&hh);
    l = *reinterpret_cast<unsigned*>(&ll);
}

// ---------------------------------------------------------------------------
// Single fused kernel. CTA = (b, i_node):
//   Phase 1 (tensor): agg[d] = sum_{j,dp} relu(E@W + b)[j, d*64+dp] * mask_j*nodes[j,dp]
//   Phase 2 (tail):   both GRU steps for row (b,i), write d_out directly.
// ---------------------------------------------------------------------------
__global__ void __launch_bounds__(256, 2)
fused_kernel(const float* __restrict__ nodes,
             const float* __restrict__ edges,
             const float* __restrict__ mask,
             const float* __restrict__ b_e,
             const float* __restrict__ K,
             const float* __restrict__ R,
             const float* __restrict__ bias,
             float* __restrict__ out)
{
    const int cta = blockIdx.x;    // b*64 + i
    const int b   = cta >> 6;
    const int i   = cta & 63;

    __shared__ __align__(16) float Mn[NN][DD];   // mask[j]*nodes[j][dp], 16 KB
    __shared__ float agg_s[DD];
    __shared__ float x1s[DD];
    __shared__ float h1s[DD];
    __shared__ float red[6][4][DD];              // split-k partials, 6 KB

    const int tid = threadIdx.x;
    {
        const float* nb = nodes + (size_t)b * NN * DD;
        const float* mb = mask  + (size_t)b * NN * NN + (size_t)i * NN;
        for (int idx = tid; idx < NN * DD; idx += 256) {
            int j  = idx >> 6;
            int dp = idx & 63;
            Mn[j][dp] = mb[j] * nb[j * DD + dp];
        }
        if (tid < DD)
            x1s[tid] = nb[i * DD + tid];
    }
    __syncthreads();

    const int warp = tid >> 5;
    const int lane = tid & 31;
    const int qid  = lane >> 2;    // 0..7
    const int tq   = lane & 3;     // 0..3

    // ---- A fragments: load fp32 edges, split to bf16 hi/lo in registers ----
    const float* Ef = edges + ((size_t)b * NN * NN + (size_t)i * NN) * EE;
    unsigned ah[4][2][4], al[4][2][4];
#pragma unroll
    for (int m = 0; m < 4; m++) {
#pragma unroll
        for (int kt = 0; kt < 2; kt++) {
            const int j0 = m * 16 + qid;
            const int k0 = kt * 16 + tq * 2;
            split2(*(const float2*)(Ef + (size_t)j0 * EE + k0),
                   ah[m][kt][0], al[m][kt][0]);
            split2(*(const float2*)(Ef + (size_t)(j0 + 8) * EE + k0),
                   ah[m][kt][1], al[m][kt][1]);
            split2(*(const float2*)(Ef + (size_t)j0 * EE + k0 + 8),
                   ah[m][kt][2], al[m][kt][2]);
            split2(*(const float2*)(Ef + (size_t)(j0 + 8) * EE + k0 + 8),
                   ah[m][kt][3], al[m][kt][3]);
        }
    }

    // ---- Phase 1: per-warp d sweep ----
    for (int dd = 0; dd < 8; dd++) {
        const int d = warp * 8 + dd;
        float acc = 0.f;

#pragma unroll
        for (int nt = 0; nt < 8; nt++) {
            const int dp0 = nt * 8 + tq * 2;
            const float2 bia = *(const float2*)&b_e[d * 64 + dp0];

            float c[4][4];
#pragma unroll
            for (int m = 0; m < 4; m++) {
                c[m][0] = bia.x; c[m][1] = bia.y;
                c[m][2] = bia.x; c[m][3] = bia.y;
            }

#pragma unroll
            for (int kt = 0; kt < 2; kt++) {
                const int ncol = d * 64 + nt * 8 + qid;
                const __nv_bfloat16* base = g_W + (size_t)ncol * 64 + kt * 32;
                const unsigned bh0 = *(const unsigned*)(base + tq * 2);
                const unsigned bh1 = *(const unsigned*)(base + 8 + tq * 2);
                const unsigned bl0 = *(const unsigned*)(base + 16 + tq * 2);
                const unsigned bl1 = *(const unsigned*)(base + 24 + tq * 2);

#pragma unroll
                for (int m = 0; m < 4; m++) {
                    MMA_BF16(c[m], ah[m][kt], bh0, bh1);
                    MMA_BF16(c[m], ah[m][kt], bl0, bl1);
                    MMA_BF16(c[m], al[m][kt], bh0, bh1);
                }
            }

#pragma unroll
            for (int m = 0; m < 4; m++) {
                const int j0 = m * 16 + qid;
                const float2 mn0 = *(const float2*)&Mn[j0][dp0];
                const float2 mn1 = *(const float2*)&Mn[j0 + 8][dp0];
                acc = fmaf(fmaxf(c[m][0], 0.f), mn0.x, acc);
                acc = fmaf(fmaxf(c[m][1], 0.f), mn0.y, acc);
                acc = fmaf(fmaxf(c[m][2], 0.f), mn1.x, acc);
                acc = fmaf(fmaxf(c[m][3], 0.f), mn1.y, acc);
            }
        }

#pragma unroll
        for (int off = 16; off; off >>= 1)
            acc += __shfl_xor_sync(0xffffffffu, acc, off);
        if (lane == 0)
            agg_s[d] = acc;
    }
    __syncthreads();

    // ---- Phase 2: GRU (two steps) for row (b,i) ----
    const int d    = tid & 63;
    const int part = tid >> 6;     // 0..3, 16 k each
    const int kk0  = part * 16;

    // step 1: h = 0
    {
        float xz = 0.f, xr = 0.f, xh = 0.f;
#pragma unroll 4
        for (int k = kk0; k < kk0 + 16; k++) {
            const float  xv = x1s[k];
            const float* Kr = K + k * 192;
            xz = fmaf(xv, Kr[d],       xz);
            xr = fmaf(xv, Kr[64 + d],  xr);
            xh = fmaf(xv, Kr[128 + d], xh);
        }
        red[0][part][d] = xz; red[1][part][d] = xr; red[2][part][d] = xh;
    }
    __syncthreads();
    if (part == 0) {
        const float xz = red[0][0][d] + red[0][1][d] + red[0][2][d] + red[0][3][d]
                       + bias[d];
        const float xr = red[1][0][d] + red[1][1][d] + red[1][2][d] + red[1][3][d]
                       + bias[64 + d];
        const float xh = red[2][0][d] + red[2][1][d] + red[2][2][d] + red[2][3][d]
                       + bias[128 + d];
        const float z  = 1.f / (1.f + expf(-(xz + bias[192 + d])));
        const float r  = 1.f / (1.f + expf(-(xr + bias[256 + d])));
        const float hh = tanhf(xh + r * bias[320 + d]);
        h1s[d] = (1.f - z) * hh;
    }
    __syncthreads();

    // step 2: x = agg, h = h1
    {
        float xz = 0.f, xr = 0.f, xh = 0.f, hz = 0.f, hr = 0.f, hl = 0.f;
#pragma unroll 4
        for (int k = kk0; k < kk0 + 16; k++) {
            const float  xv = agg_s[k];
            const float  hv = h1s[k];
            const float* Kr = K + k * 192;
            const float* Rr = R + k * 192;
            xz = fmaf(xv, Kr[d],       xz);
            xr = fmaf(xv, Kr[64 + d],  xr);
            xh = fmaf(xv, Kr[128 + d], xh);
            hz = fmaf(hv, Rr[d],       hz);
            hr = fmaf(hv, Rr[64 + d],  hr);
            hl = fmaf(hv, Rr[128 + d], hl);
        }
        red[0][part][d] = xz; red[1][part][d] = xr; red[2][part][d] = xh;
        red[3][part][d] = hz; red[4][part][d] = hr; red[5][part][d] = hl;
    }
    __syncthreads();
    if (part == 0) {
        const float xz = red[0][0][d] + red[0][1][d] + red[0][2][d] + red[0][3][d]
                       + bias[d];
        const float xr = red[1][0][d] + red[1][1][d] + red[1][2][d] + red[1][3][d]
                       + bias[64 + d];
        const float xh = red[2][0][d] + red[2][1][d] + red[2][2][d] + red[2][3][d]
                       + bias[128 + d];
        const float hz = red[3][0][d] + red[3][1][d] + red[3][2][d] + red[3][3][d]
                       + bias[192 + d];
        const float hr = red[4][0][d] + red[4][1][d] + red[4][2][d] + red[4][3][d]
                       + bias[256 + d];
        const float hl = red[5][0][d] + red[5][1][d] + red[5][2][d] + red[5][3][d]
                       + bias[320 + d];
        const float z  = 1.f / (1.f + expf(-(xz + hz)));
        const float r  = 1.f / (1.f + expf(-(xr + hr)));
        const float hh = tanhf(xh + r * hl);
        const float h1 = h1s[d];
        out[(size_t)cta * DD + d] = z * h1 + (1.f - z) * hh;
    }
}

// ---------------------------------------------------------------------------
extern "C" void kernel_launch(void* const* d_in, const int* in_sizes, int n_in,
                              void* d_out, int out_size)
{
    const float* nodes  = (const float*)d_in[0];
    const float* edges  = (const float*)d_in[1];
    const float* mask   = (const float*)d_in[2];
    const float* W_e    = (const float*)d_in[3];
    const float* b_e    = (const float*)d_in[4];
    const float* gruK   = (const float*)d_in[5];
    const float* gruR   = (const float*)d_in[6];
    const float* gruB   = (const float*)d_in[7];
    float*       out    = (float*)d_out;

    prep_w_kernel<<<(EE * DD * DD + 255) / 256, 256>>>(W_e);
    fused_kernel<<<BB * NN, 256>>>(nodes, edges, mask, b_e,
                                   gruK, gruR, gruB, out);
}

// round 6
// speedup vs baseline: 2.2118x; 2.2118x over previous
#include <cuda_runtime.h>
#include <cuda_bf16.h>

#define BB 8
#define NN 64
#define DD 64
#define EE 32

// ---------------------------------------------------------------------------
// W_e transposed + split bf16 hi/lo, packed so each mma B-fragment is ONE
// 16-byte load per lane. Per column (4096 cols, 128 B each):
//   for kt in {0,1}:  for tq in {0..3}:
//     16 B = { h(2tq),h(2tq+1), h(2tq+8),h(2tq+9), l(2tq),l(2tq+1), l(2tq+8),l(2tq+9) }
//     (k indices relative to kt*16)
// ---------------------------------------------------------------------------
__device__ __nv_bfloat16 g_W[DD * DD * EE * 2];   // 4096 cols x 64 bf16

__global__ void prep_w_kernel(const float* __restrict__ W_e)
{
    int idx = blockIdx.x * blockDim.x + threadIdx.x;   // over 32*4096
    if (idx >= EE * DD * DD) return;
    int k   = idx >> 12;          // 0..31
    int col = idx & 4095;
    float x = W_e[idx];
    __nv_bfloat16 h = __float2bfloat16(x);
    float lo = x - __bfloat162float(h);

    int kt = k >> 4;
    int kr = k & 15;
    int tq, pos;
    if (kr < 8) { tq = kr >> 1;       pos = kr & 1; }
    else        { tq = (kr - 8) >> 1; pos = 2 + (kr & 1); }

    __nv_bfloat16* base = g_W + (size_t)col * 64 + kt * 32 + tq * 8;
    base[pos]     = h;                      // hi slots 0..3
    base[4 + pos] = __float2bfloat16(lo);   // lo slots 4..7
}

// ---------------------------------------------------------------------------
#define MMA_BF16(C, A, b0, b1)                                                 \
    asm volatile(                                                              \
        "mma.sync.aligned.m16n8k16.row.col.f32.bf16.bf16.f32 "                 \
        "{%0,%1,%2,%3}, {%4,%5,%6,%7}, {%8,%9}, {%0,%1,%2,%3};"                \
        : "+f"((C)[0]), "+f"((C)[1]), "+f"((C)[2]), "+f"((C)[3])               \
        : "r"((A)[0]), "r"((A)[1]), "r"((A)[2]), "r"((A)[3]),                  \
          "r"(b0), "r"(b1))

__device__ __forceinline__ void split2(float2 v, unsigned& h, unsigned& l)
{
    __nv_bfloat16 hx = __float2bfloat16(v.x);
    __nv_bfloat16 hy = __float2bfloat16(v.y);
    float lx = v.x - __bfloat162float(hx);
    float ly = v.y - __bfloat162float(hy);
    __nv_bfloat162 hh = __halves2bfloat162(hx, hy);
    __nv_bfloat162 ll = __halves2bfloat162(__float2bfloat16(lx),
                                           __float2bfloat16(ly));
    h = *reinterpret_cast<unsigned*>(&hh);
    l = *reinterpret_cast<unsigned*>(&ll);
}

// ---------------------------------------------------------------------------
// Single fused kernel. CTA = (b, i_node):
//   Phase 1 (tensor): agg[d] = sum_{j,dp} relu(E@W + b)[j, d*64+dp] * mask_j*nodes[j,dp]
//   Phase 2 (tail):   both GRU steps for row (b,i), write d_out directly.
// NO min-blocks hint: spills killed R5 (regs capped at 128 -> local mem).
// ---------------------------------------------------------------------------
__global__ void __launch_bounds__(256)
fused_kernel(const float* __restrict__ nodes,
             const float* __restrict__ edges,
             const float* __restrict__ mask,
             const float* __restrict__ b_e,
             const float* __restrict__ K,
             const float* __restrict__ R,
             const float* __restrict__ bias,
             float* __restrict__ out)
{
    const int cta = blockIdx.x;    // b*64 + i
    const int b   = cta >> 6;
    const int i   = cta & 63;

    __shared__ __align__(16) float Mn[NN][DD];   // mask[j]*nodes[j][dp], 16 KB
    __shared__ float agg_s[DD];
    __shared__ float x1s[DD];
    __shared__ float h1s[DD];
    __shared__ float red[6][4][DD];              // split-k partials, 6 KB

    const int tid = threadIdx.x;
    {
        const float* nb = nodes + (size_t)b * NN * DD;
        const float* mb = mask  + (size_t)b * NN * NN + (size_t)i * NN;
        for (int idx = tid; idx < NN * DD; idx += 256) {
            int j  = idx >> 6;
            int dp = idx & 63;
            Mn[j][dp] = mb[j] * nb[j * DD + dp];
        }
        if (tid < DD)
            x1s[tid] = nb[i * DD + tid];
    }
    __syncthreads();

    const int warp = tid >> 5;
    const int lane = tid & 31;
    const int qid  = lane >> 2;    // 0..7
    const int tq   = lane & 3;     // 0..3

    // ---- A fragments: load fp32 edges, split to bf16 hi/lo in registers ----
    const float* Ef = edges + ((size_t)b * NN * NN + (size_t)i * NN) * EE;
    unsigned ah[4][2][4], al[4][2][4];
#pragma unroll
    for (int m = 0; m < 4; m++) {
#pragma unroll
        for (int kt = 0; kt < 2; kt++) {
            const int j0 = m * 16 + qid;
            const int k0 = kt * 16 + tq * 2;
            split2(*(const float2*)(Ef + (size_t)j0 * EE + k0),
                   ah[m][kt][0], al[m][kt][0]);
            split2(*(const float2*)(Ef + (size_t)(j0 + 8) * EE + k0),
                   ah[m][kt][1], al[m][kt][1]);
            split2(*(const float2*)(Ef + (size_t)j0 * EE + k0 + 8),
                   ah[m][kt][2], al[m][kt][2]);
            split2(*(const float2*)(Ef + (size_t)(j0 + 8) * EE + k0 + 8),
                   ah[m][kt][3], al[m][kt][3]);
        }
    }

    // ---- Phase 1: per-warp d sweep ----
    for (int dd = 0; dd < 8; dd++) {
        const int d = warp * 8 + dd;
        float acc = 0.f;

#pragma unroll
        for (int nt = 0; nt < 8; nt++) {
            const int dp0 = nt * 8 + tq * 2;
            const float2 bia = *(const float2*)&b_e[d * 64 + dp0];

            float c[4][4];
#pragma unroll
            for (int m = 0; m < 4; m++) {
                c[m][0] = bia.x; c[m][1] = bia.y;
                c[m][2] = bia.x; c[m][3] = bia.y;
            }

#pragma unroll
            for (int kt = 0; kt < 2; kt++) {
                const int ncol = d * 64 + nt * 8 + qid;
                const uint4 w = *(const uint4*)(g_W + (size_t)ncol * 64
                                                + kt * 32 + tq * 8);
                // w.x = bh0, w.y = bh1, w.z = bl0, w.w = bl1
#pragma unroll
                for (int m = 0; m < 4; m++) {
                    MMA_BF16(c[m], ah[m][kt], w.x, w.y);
                    MMA_BF16(c[m], ah[m][kt], w.z, w.w);
                    MMA_BF16(c[m], al[m][kt], w.x, w.y);
                }
            }

#pragma unroll
            for (int m = 0; m < 4; m++) {
                const int j0 = m * 16 + qid;
                const float2 mn0 = *(const float2*)&Mn[j0][dp0];
                const float2 mn1 = *(const float2*)&Mn[j0 + 8][dp0];
                acc = fmaf(fmaxf(c[m][0], 0.f), mn0.x, acc);
                acc = fmaf(fmaxf(c[m][1], 0.f), mn0.y, acc);
                acc = fmaf(fmaxf(c[m][2], 0.f), mn1.x, acc);
                acc = fmaf(fmaxf(c[m][3], 0.f), mn1.y, acc);
            }
        }

#pragma unroll
        for (int off = 16; off; off >>= 1)
            acc += __shfl_xor_sync(0xffffffffu, acc, off);
        if (lane == 0)
            agg_s[d] = acc;
    }
    __syncthreads();

    // ---- Phase 2: GRU (two steps) for row (b,i) ----
    const int d    = tid & 63;
    const int part = tid >> 6;     // 0..3, 16 k each
    const int kk0  = part * 16;

    // step 1: h = 0
    {
        float xz = 0.f, xr = 0.f, xh = 0.f;
#pragma unroll 4
        for (int k = kk0; k < kk0 + 16; k++) {
            const float  xv = x1s[k];
            const float* Kr = K + k * 192;
            xz = fmaf(xv, Kr[d],       xz);
            xr = fmaf(xv, Kr[64 + d],  xr);
            xh = fmaf(xv, Kr[128 + d], xh);
        }
        red[0][part][d] = xz; red[1][part][d] = xr; red[2][part][d] = xh;
    }
    __syncthreads();
    if (part == 0) {
        const float xz = red[0][0][d] + red[0][1][d] + red[0][2][d] + red[0][3][d]
                       + bias[d];
        const float xr = red[1][0][d] + red[1][1][d] + red[1][2][d] + red[1][3][d]
                       + bias[64 + d];
        const float xh = red[2][0][d] + red[2][1][d] + red[2][2][d] + red[2][3][d]
                       + bias[128 + d];
        const float z  = 1.f / (1.f + expf(-(xz + bias[192 + d])));
        const float r  = 1.f / (1.f + expf(-(xr + bias[256 + d])));
        const float hh = tanhf(xh + r * bias[320 + d]);
        h1s[d] = (1.f - z) * hh;
    }
    __syncthreads();

    // step 2: x = agg, h = h1
    {
        float xz = 0.f, xr = 0.f, xh = 0.f, hz = 0.f, hr = 0.f, hl = 0.f;
#pragma unroll 4
        for (int k = kk0; k < kk0 + 16; k++) {
            const float  xv = agg_s[k];
            const float  hv = h1s[k];
            const float* Kr = K + k * 192;
            const float* Rr = R + k * 192;
            xz = fmaf(xv, Kr[d],       xz);
            xr = fmaf(xv, Kr[64 + d],  xr);
            xh = fmaf(xv, Kr[128 + d], xh);
            hz = fmaf(hv, Rr[d],       hz);
            hr = fmaf(hv, Rr[64 + d],  hr);
            hl = fmaf(hv, Rr[128 + d], hl);
        }
        red[0][part][d] = xz; red[1][part][d] = xr; red[2][part][d] = xh;
        red[3][part][d] = hz; red[4][part][d] = hr; red[5][part][d] = hl;
    }
    __syncthreads();
    if (part == 0) {
        const float xz = red[0][0][d] + red[0][1][d] + red[0][2][d] + red[0][3][d]
                       + bias[d];
        const float xr = red[1][0][d] + red[1][1][d] + red[1][2][d] + red[1][3][d]
                       + bias[64 + d];
        const float xh = red[2][0][d] + red[2][1][d] + red[2][2][d] + red[2][3][d]
                       + bias[128 + d];
        const float hz = red[3][0][d] + red[3][1][d] + red[3][2][d] + red[3][3][d]
                       + bias[192 + d];
        const float hr = red[4][0][d] + red[4][1][d] + red[4][2][d] + red[4][3][d]
                       + bias[256 + d];
        const float hl = red[5][0][d] + red[5][1][d] + red[5][2][d] + red[5][3][d]
                       + bias[320 + d];
        const float z  = 1.f / (1.f + expf(-(xz + hz)));
        const float r  = 1.f / (1.f + expf(-(xr + hr)));
        const float hh = tanhf(xh + r * hl);
        const float h1 = h1s[d];
        out[(size_t)cta * DD + d] = z * h1 + (1.f - z) * hh;
    }
}

// ---------------------------------------------------------------------------
extern "C" void kernel_launch(void* const* d_in, const int* in_sizes, int n_in,
                              void* d_out, int out_size)
{
    const float* nodes  = (const float*)d_in[0];
    const float* edges  = (const float*)d_in[1];
    const float* mask   = (const float*)d_in[2];
    const float* W_e    = (const float*)d_in[3];
    const float* b_e    = (const float*)d_in[4];
    const float* gruK   = (const float*)d_in[5];
    const float* gruR   = (const float*)d_in[6];
    const float* gruB   = (const float*)d_in[7];
    float*       out    = (float*)d_out;

    prep_w_kernel<<<(EE * DD * DD + 255) / 256, 256>>>(W_e);
    fused_kernel<<<BB * NN, 256>>>(nodes, edges, mask, b_e,
                                   gruK, gruR, gruB, out);
}

// round 8
// speedup vs baseline: 3.7007x; 1.6732x over previous
#include <cuda_runtime.h>
#include <cuda_fp16.h>
#include <cuda_bf16.h>

#define BB 8
#define NN 64
#define DD 64
#define EE 32

// ---------------------------------------------------------------------------
// W_e transposed to [col][k], fp16, packed so ONE 16-byte load per lane gives
// the B-fragments for BOTH k-tiles of a column:
//   per column (32 fp16 = 64 B), per tq (0..3), 16 B =
//     { kt0: h(2tq),h(2tq+1),h(2tq+8),h(2tq+9),
//       kt1: h(2tq),h(2tq+1),h(2tq+8),h(2tq+9) }   (k rel. to kt*16)
// ---------------------------------------------------------------------------
__device__ __half g_Wh[DD * DD * EE];   // 4096 cols x 32 fp16 = 256 KB

__global__ void prep_w_kernel(const float* __restrict__ W_e)
{
    int idx = blockIdx.x * blockDim.x + threadIdx.x;   // over 32*4096
    if (idx >= EE * DD * DD) return;
    int k   = idx >> 12;          // 0..31
    int col = idx & 4095;
    int kt  = k >> 4;
    int kr  = k & 15;
    int tq  = (kr < 8) ? (kr >> 1) : ((kr - 8) >> 1);
    int pos = (kr < 8) ? (kr & 1) : (2 + (kr & 1));
    g_Wh[(size_t)col * 32 + tq * 8 + kt * 4 + pos] = __float2half(W_e[idx]);
}

// ---------------------------------------------------------------------------
#define MMA_F16(C, A, b0, b1)                                                  \
    asm volatile(                                                              \
        "mma.sync.aligned.m16n8k16.row.col.f32.f16.f16.f32 "                   \
        "{%0,%1,%2,%3}, {%4,%5,%6,%7}, {%8,%9}, {%0,%1,%2,%3};"                \
        : "+f"((C)[0]), "+f"((C)[1]), "+f"((C)[2]), "+f"((C)[3])               \
        : "r"((A)[0]), "r"((A)[1]), "r"((A)[2]), "r"((A)[3]),                  \
          "r"(b0), "r"(b1))

__device__ __forceinline__ unsigned pack_h2(float2 v)
{
    __half2 h = __float22half2_rn(v);
    return *reinterpret_cast<unsigned*>(&h);
}

// ---------------------------------------------------------------------------
// Single fused kernel. CTA = (b, i_node):
//   Phase 1 (tensor): agg[d] = sum_{j,dp} relu(E@W + b)[j, d*64+dp] * mask_j*nodes[j,dp]
//   Phase 2 (tail):   both GRU steps for row (b,i), write d_out directly.
// nt is OUTER loop so Mn smem loads are hoisted out of the d sweep (8x fewer
// LDS), and Mn rows are padded (+4) to break the 8-way bank conflicts.
// ---------------------------------------------------------------------------
#define DPAD (DD + 4)

__global__ void __launch_bounds__(256)
fused_kernel(const float* __restrict__ nodes,
             const float* __restrict__ edges,
             const float* __restrict__ mask,
             const float* __restrict__ b_e,
             const float* __restrict__ K,
             const float* __restrict__ R,
             const float* __restrict__ bias,
             float* __restrict__ out)
{
    const int cta = blockIdx.x;    // b*64 + i
    const int b   = cta >> 6;
    const int i   = cta & 63;

    __shared__ __align__(16) float Mn[NN][DPAD];   // mask[j]*nodes[j][dp]
    __shared__ float agg_s[DD];
    __shared__ float x1s[DD];
    __shared__ float h1s[DD];
    __shared__ float red[6][4][DD];                // split-k partials

    const int tid = threadIdx.x;
    {
        const float* nb = nodes + (size_t)b * NN * DD;
        const float* mb = mask  + (size_t)b * NN * NN + (size_t)i * NN;
        for (int idx = tid; idx < NN * DD; idx += 256) {
            int j  = idx >> 6;
            int dp = idx & 63;
            Mn[j][dp] = mb[j] * nb[j * DD + dp];
        }
        if (tid < DD)
            x1s[tid] = nb[i * DD + tid];
    }
    __syncthreads();

    const int warp = tid >> 5;
    const int lane = tid & 31;
    const int qid  = lane >> 2;    // 0..7
    const int tq   = lane & 3;     // 0..3

    // ---- A fragments: fp32 edges -> fp16 in registers ----
    const float* Ef = edges + ((size_t)b * NN * NN + (size_t)i * NN) * EE;
    unsigned ah[4][2][4];
#pragma unroll
    for (int m = 0; m < 4; m++) {
#pragma unroll
        for (int kt = 0; kt < 2; kt++) {
            const int j0 = m * 16 + qid;
            const int k0 = kt * 16 + tq * 2;
            ah[m][kt][0] = pack_h2(*(const float2*)(Ef + (size_t)j0 * EE + k0));
            ah[m][kt][1] = pack_h2(*(const float2*)(Ef + (size_t)(j0 + 8) * EE + k0));
            ah[m][kt][2] = pack_h2(*(const float2*)(Ef + (size_t)j0 * EE + k0 + 8));
            ah[m][kt][3] = pack_h2(*(const float2*)(Ef + (size_t)(j0 + 8) * EE + k0 + 8));
        }
    }

    // ---- Phase 1: nt outer, d inner ----
    float acc[8];
#pragma unroll
    for (int dd = 0; dd < 8; dd++) acc[dd] = 0.f;

    for (int nt = 0; nt < 8; nt++) {
        const int dp0 = nt * 8 + tq * 2;

        float2 mn[4][2];
#pragma unroll
        for (int m = 0; m < 4; m++) {
            const int j0 = m * 16 + qid;
            mn[m][0] = *(const float2*)&Mn[j0][dp0];
            mn[m][1] = *(const float2*)&Mn[j0 + 8][dp0];
        }

#pragma unroll
        for (int dd = 0; dd < 8; dd++) {
            const int d    = warp * 8 + dd;
            const int ncol = d * 64 + nt * 8 + qid;
            const uint4 w = *(const uint4*)(g_Wh + (size_t)ncol * 32 + tq * 8);
            const float2 bia = *(const float2*)&b_e[d * 64 + dp0];

            float c[4][4];
#pragma unroll
            for (int m = 0; m < 4; m++) {
                c[m][0] = bia.x; c[m][1] = bia.y;
                c[m][2] = bia.x; c[m][3] = bia.y;
            }
#pragma unroll
            for (int m = 0; m < 4; m++)
                MMA_F16(c[m], ah[m][0], w.x, w.y);
#pragma unroll
            for (int m = 0; m < 4; m++)
                MMA_F16(c[m], ah[m][1], w.z, w.w);

            float a = acc[dd];
#pragma unroll
            for (int m = 0; m < 4; m++) {
                a = fmaf(fmaxf(c[m][0], 0.f), mn[m][0].x, a);
                a = fmaf(fmaxf(c[m][1], 0.f), mn[m][0].y, a);
                a = fmaf(fmaxf(c[m][2], 0.f), mn[m][1].x, a);
                a = fmaf(fmaxf(c[m][3], 0.f), mn[m][1].y, a);
            }
            acc[dd] = a;
        }
    }

#pragma unroll
    for (int dd = 0; dd < 8; dd++) {
        float a = acc[dd];
#pragma unroll
        for (int off = 16; off; off >>= 1)
            a += __shfl_xor_sync(0xffffffffu, a, off);
        if (lane == 0)
            agg_s[warp * 8 + dd] = a;
    }
    __syncthreads();

    // ---- Phase 2: GRU (two steps) for row (b,i) ----
    const int d    = tid & 63;
    const int part = tid >> 6;     // 0..3, 16 k each
    const int kk0  = part * 16;

    // step 1: h = 0
    {
        float xz = 0.f, xr = 0.f, xh = 0.f;
#pragma unroll 4
        for (int k = kk0; k < kk0 + 16; k++) {
            const float  xv = x1s[k];
            const float* Kr = K + k * 192;
            xz = fmaf(xv, Kr[d],       xz);
            xr = fmaf(xv, Kr[64 + d],  xr);
            xh = fmaf(xv, Kr[128 + d], xh);
        }
        red[0][part][d] = xz; red[1][part][d] = xr; red[2][part][d] = xh;
    }
    __syncthreads();
    if (part == 0) {
        const float xz = red[0][0][d] + red[0][1][d] + red[0][2][d] + red[0][3][d]
                       + bias[d];
        const float xr = red[1][0][d] + red[1][1][d] + red[1][2][d] + red[1][3][d]
                       + bias[64 + d];
        const float xh = red[2][0][d] + red[2][1][d] + red[2][2][d] + red[2][3][d]
                       + bias[128 + d];
        const float z  = 1.f / (1.f + expf(-(xz + bias[192 + d])));
        const float r  = 1.f / (1.f + expf(-(xr + bias[256 + d])));
        const float hh = tanhf(xh + r * bias[320 + d]);
        h1s[d] = (1.f - z) * hh;
    }
    __syncthreads();

    // step 2: x = agg, h = h1
    {
        float xz = 0.f, xr = 0.f, xh = 0.f, hz = 0.f, hr = 0.f, hl = 0.f;
#pragma unroll 4
        for (int k = kk0; k < kk0 + 16; k++) {
            const float  xv = agg_s[k];
            const float  hv = h1s[k];
            const float* Kr = K + k * 192;
            const float* Rr = R + k * 192;
            xz = fmaf(xv, Kr[d],       xz);
            xr = fmaf(xv, Kr[64 + d],  xr);
            xh = fmaf(xv, Kr[128 + d], xh);
            hz = fmaf(hv, Rr[d],       hz);
            hr = fmaf(hv, Rr[64 + d],  hr);
            hl = fmaf(hv, Rr[128 + d], hl);
        }
        red[0][part][d] = xz; red[1][part][d] = xr; red[2][part][d] = xh;
        red[3][part][d] = hz; red[4][part][d] = hr; red[5][part][d] = hl;
    }
    __syncthreads();
    if (part == 0) {
        const float xz = red[0][0][d] + red[0][1][d] + red[0][2][d] + red[0][3][d]
                       + bias[d];
        const float xr = red[1][0][d] + red[1][1][d] + red[1][2][d] + red[1][3][d]
                       + bias[64 + d];
        const float xh = red[2][0][d] + red[2][1][d] + red[2][2][d] + red[2][3][d]
                       + bias[128 + d];
        const float hz = red[3][0][d] + red[3][1][d] + red[3][2][d] + red[3][3][d]
                       + bias[192 + d];
        const float hr = red[4][0][d] + red[4][1][d] + red[4][2][d] + red[4][3][d]
                       + bias[256 + d];
        const float hl = red[5][0][d] + red[5][1][d] + red[5][2][d] + red[5][3][d]
                       + bias[320 + d];
        const float z  = 1.f / (1.f + expf(-(xz + hz)));
        const float r  = 1.f / (1.f + expf(-(xr + hr)));
        const float hh = tanhf(xh + r * hl);
        const float h1 = h1s[d];
        out[(size_t)cta * DD + d] = z * h1 + (1.f - z) * hh;
    }
}

// ---------------------------------------------------------------------------
extern "C" void kernel_launch(void* const* d_in, const int* in_sizes, int n_in,
                              void* d_out, int out_size)
{
    const float* nodes  = (const float*)d_in[0];
    const float* edges  = (const float*)d_in[1];
    const float* mask   = (const float*)d_in[2];
    const float* W_e    = (const float*)d_in[3];
    const float* b_e    = (const float*)d_in[4];
    const float* gruK   = (const float*)d_in[5];
    const float* gruR   = (const float*)d_in[6];
    const float* gruB   = (const float*)d_in[7];
    float*       out    = (float*)d_out;

    prep_w_kernel<<<(EE * DD * DD + 255) / 256, 256>>>(W_e);
    fused_kernel<<<BB * NN, 256>>>(nodes, edges, mask, b_e,
                                   gruK, gruR, gruB, out);
}

// round 9
// speedup vs baseline: 4.3711x; 1.1812x over previous
#include <cuda_runtime.h>
#include <cuda_fp16.h>
#include <cuda_bf16.h>

#define BB 8
#define NN 64
#define DD 64
#define EE 32

// ---------------------------------------------------------------------------
// W_e transposed to [col][k], fp16, packed so ONE 16-byte load per lane gives
// the B-fragments for BOTH k-tiles of a column:
//   per column (32 fp16 = 64 B), per tq (0..3), 16 B =
//     { kt0: h(2tq),h(2tq+1),h(2tq+8),h(2tq+9),
//       kt1: h(2tq),h(2tq+1),h(2tq+8),h(2tq+9) }   (k rel. to kt*16)
// ---------------------------------------------------------------------------
__device__ __half g_Wh[DD * DD * EE];   // 4096 cols x 32 fp16 = 256 KB

__global__ void prep_w_kernel(const float* __restrict__ W_e)
{
    int idx = blockIdx.x * blockDim.x + threadIdx.x;   // over 32*4096
    if (idx >= EE * DD * DD) return;
    int k   = idx >> 12;          // 0..31
    int col = idx & 4095;
    int kt  = k >> 4;
    int kr  = k & 15;
    int tq  = (kr < 8) ? (kr >> 1) : ((kr - 8) >> 1);
    int pos = (kr < 8) ? (kr & 1) : (2 + (kr & 1));
    g_Wh[(size_t)col * 32 + tq * 8 + kt * 4 + pos] = __float2half(W_e[idx]);
}

// ---------------------------------------------------------------------------
#define MMA_F16(C, A, b0, b1)                                                  \
    asm volatile(                                                              \
        "mma.sync.aligned.m16n8k16.row.col.f32.f16.f16.f32 "                   \
        "{%0,%1,%2,%3}, {%4,%5,%6,%7}, {%8,%9}, {%0,%1,%2,%3};"                \
        : "+f"((C)[0]), "+f"((C)[1]), "+f"((C)[2]), "+f"((C)[3])               \
        : "r"((A)[0]), "r"((A)[1]), "r"((A)[2]), "r"((A)[3]),                  \
          "r"(b0), "r"(b1))

__device__ __forceinline__ unsigned pack_h2(float2 v)
{
    __half2 h = __float22half2_rn(v);
    return *reinterpret_cast<unsigned*>(&h);
}

// ---------------------------------------------------------------------------
// Single fused kernel. CTA = (b, i_node):
//   Phase 1 (tensor): agg[d] = sum_{j,dp} relu(E@W + b)[j, d*64+dp] * mask_j*nodes[j,dp]
//   Phase 2 (tail):   both GRU steps for row (b,i), write d_out directly.
// Epilogue uses 2 parallel FMA chains per dd (was 1x16-deep serial chain -> the
// dominant latency in R8); nt loop unrolled x2 for load/compute overlap.
// ---------------------------------------------------------------------------
#define DPAD (DD + 4)

__global__ void __launch_bounds__(256)
fused_kernel(const float* __restrict__ nodes,
             const float* __restrict__ edges,
             const float* __restrict__ mask,
             const float* __restrict__ b_e,
             const float* __restrict__ K,
             const float* __restrict__ R,
             const float* __restrict__ bias,
             float* __restrict__ out)
{
    const int cta = blockIdx.x;    // b*64 + i
    const int b   = cta >> 6;
    const int i   = cta & 63;

    __shared__ __align__(16) float Mn[NN][DPAD];   // mask[j]*nodes[j][dp]
    __shared__ float agg_s[DD];
    __shared__ float x1s[DD];
    __shared__ float h1s[DD];
    __shared__ float red[6][4][DD];                // split-k partials

    const int tid = threadIdx.x;
    {
        const float* nb = nodes + (size_t)b * NN * DD;
        const float* mb = mask  + (size_t)b * NN * NN + (size_t)i * NN;
        for (int idx = tid; idx < NN * DD; idx += 256) {
            int j  = idx >> 6;
            int dp = idx & 63;
            Mn[j][dp] = mb[j] * nb[j * DD + dp];
        }
        if (tid < DD)
            x1s[tid] = nb[i * DD + tid];
    }
    __syncthreads();

    const int warp = tid >> 5;
    const int lane = tid & 31;
    const int qid  = lane >> 2;    // 0..7
    const int tq   = lane & 3;     // 0..3

    // ---- A fragments: fp32 edges -> fp16 in registers ----
    const float* Ef = edges + ((size_t)b * NN * NN + (size_t)i * NN) * EE;
    unsigned ah[4][2][4];
#pragma unroll
    for (int m = 0; m < 4; m++) {
#pragma unroll
        for (int kt = 0; kt < 2; kt++) {
            const int j0 = m * 16 + qid;
            const int k0 = kt * 16 + tq * 2;
            ah[m][kt][0] = pack_h2(*(const float2*)(Ef + (size_t)j0 * EE + k0));
            ah[m][kt][1] = pack_h2(*(const float2*)(Ef + (size_t)(j0 + 8) * EE + k0));
            ah[m][kt][2] = pack_h2(*(const float2*)(Ef + (size_t)j0 * EE + k0 + 8));
            ah[m][kt][3] = pack_h2(*(const float2*)(Ef + (size_t)(j0 + 8) * EE + k0 + 8));
        }
    }

    // ---- Phase 1: nt outer (unroll 2), d inner; 2 acc chains per dd ----
    float acc2[8][2];
#pragma unroll
    for (int dd = 0; dd < 8; dd++) { acc2[dd][0] = 0.f; acc2[dd][1] = 0.f; }

#pragma unroll 2
    for (int nt = 0; nt < 8; nt++) {
        const int dp0 = nt * 8 + tq * 2;

        float2 mn[4][2];
#pragma unroll
        for (int m = 0; m < 4; m++) {
            const int j0 = m * 16 + qid;
            mn[m][0] = *(const float2*)&Mn[j0][dp0];
            mn[m][1] = *(const float2*)&Mn[j0 + 8][dp0];
        }

#pragma unroll
        for (int dd = 0; dd < 8; dd++) {
            const int d    = warp * 8 + dd;
            const int ncol = d * 64 + nt * 8 + qid;
            const uint4 w = *(const uint4*)(g_Wh + (size_t)ncol * 32 + tq * 8);
            const float2 bia = *(const float2*)&b_e[d * 64 + dp0];

            float c[4][4];
#pragma unroll
            for (int m = 0; m < 4; m++) {
                c[m][0] = bia.x; c[m][1] = bia.y;
                c[m][2] = bia.x; c[m][3] = bia.y;
            }
#pragma unroll
            for (int m = 0; m < 4; m++)
                MMA_F16(c[m], ah[m][0], w.x, w.y);
#pragma unroll
            for (int m = 0; m < 4; m++)
                MMA_F16(c[m], ah[m][1], w.z, w.w);

            float a0 = acc2[dd][0];
            float a1 = acc2[dd][1];
#pragma unroll
            for (int m = 0; m < 4; m++) {
                a0 = fmaf(fmaxf(c[m][0], 0.f), mn[m][0].x, a0);
                a1 = fmaf(fmaxf(c[m][1], 0.f), mn[m][0].y, a1);
                a0 = fmaf(fmaxf(c[m][2], 0.f), mn[m][1].x, a0);
                a1 = fmaf(fmaxf(c[m][3], 0.f), mn[m][1].y, a1);
            }
            acc2[dd][0] = a0;
            acc2[dd][1] = a1;
        }
    }

#pragma unroll
    for (int dd = 0; dd < 8; dd++) {
        float a = acc2[dd][0] + acc2[dd][1];
#pragma unroll
        for (int off = 16; off; off >>= 1)
            a += __shfl_xor_sync(0xffffffffu, a, off);
        if (lane == 0)
            agg_s[warp * 8 + dd] = a;
    }
    __syncthreads();

    // ---- Phase 2: GRU (two steps) for row (b,i) ----
    const int d    = tid & 63;
    const int part = tid >> 6;     // 0..3, 16 k each
    const int kk0  = part * 16;

    // step 1: h = 0
    {
        float xz = 0.f, xr = 0.f, xh = 0.f;
#pragma unroll 4
        for (int k = kk0; k < kk0 + 16; k++) {
            const float  xv = x1s[k];
            const float* Kr = K + k * 192;
            xz = fmaf(xv, Kr[d],       xz);
            xr = fmaf(xv, Kr[64 + d],  xr);
            xh = fmaf(xv, Kr[128 + d], xh);
        }
        red[0][part][d] = xz; red[1][part][d] = xr; red[2][part][d] = xh;
    }
    __syncthreads();
    if (part == 0) {
        const float xz = red[0][0][d] + red[0][1][d] + red[0][2][d] + red[0][3][d]
                       + bias[d];
        const float xr = red[1][0][d] + red[1][1][d] + red[1][2][d] + red[1][3][d]
                       + bias[64 + d];
        const float xh = red[2][0][d] + red[2][1][d] + red[2][2][d] + red[2][3][d]
                       + bias[128 + d];
        const float z  = 1.f / (1.f + expf(-(xz + bias[192 + d])));
        const float r  = 1.f / (1.f + expf(-(xr + bias[256 + d])));
        const float hh = tanhf(xh + r * bias[320 + d]);
        h1s[d] = (1.f - z) * hh;
    }
    __syncthreads();

    // step 2: x = agg, h = h1
    {
        float xz = 0.f, xr = 0.f, xh = 0.f, hz = 0.f, hr = 0.f, hl = 0.f;
#pragma unroll 4
        for (int k = kk0; k < kk0 + 16; k++) {
            const float  xv = agg_s[k];
            const float  hv = h1s[k];
            const float* Kr = K + k * 192;
            const float* Rr = R + k * 192;
            xz = fmaf(xv, Kr[d],       xz);
            xr = fmaf(xv, Kr[64 + d],  xr);
            xh = fmaf(xv, Kr[128 + d], xh);
            hz = fmaf(hv, Rr[d],       hz);
            hr = fmaf(hv, Rr[64 + d],  hr);
            hl = fmaf(hv, Rr[128 + d], hl);
        }
        red[0][part][d] = xz; red[1][part][d] = xr; red[2][part][d] = xh;
        red[3][part][d] = hz; red[4][part][d] = hr; red[5][part][d] = hl;
    }
    __syncthreads();
    if (part == 0) {
        const float xz = red[0][0][d] + red[0][1][d] + red[0][2][d] + red[0][3][d]
                       + bias[d];
        const float xr = red[1][0][d] + red[1][1][d] + red[1][2][d] + red[1][3][d]
                       + bias[64 + d];
        const float xh = red[2][0][d] + red[2][1][d] + red[2][2][d] + red[2][3][d]
                       + bias[128 + d];
        const float hz = red[3][0][d] + red[3][1][d] + red[3][2][d] + red[3][3][d]
                       + bias[192 + d];
        const float hr = red[4][0][d] + red[4][1][d] + red[4][2][d] + red[4][3][d]
                       + bias[256 + d];
        const float hl = red[5][0][d] + red[5][1][d] + red[5][2][d] + red[5][3][d]
                       + bias[320 + d];
        const float z  = 1.f / (1.f + expf(-(xz + hz)));
        const float r  = 1.f / (1.f + expf(-(xr + hr)));
        const float hh = tanhf(xh + r * hl);
        const float h1 = h1s[d];
        out[(size_t)cta * DD + d] = z * h1 + (1.f - z) * hh;
    }
}

// ---------------------------------------------------------------------------
extern "C" void kernel_launch(void* const* d_in, const int* in_sizes, int n_in,
                              void* d_out, int out_size)
{
    const float* nodes  = (const float*)d_in[0];
    const float* edges  = (const float*)d_in[1];
    const float* mask   = (const float*)d_in[2];
    const float* W_e    = (const float*)d_in[3];
    const float* b_e    = (const float*)d_in[4];
    const float* gruK   = (const float*)d_in[5];
    const float* gruR   = (const float*)d_in[6];
    const float* gruB   = (const float*)d_in[7];
    float*       out    = (float*)d_out;

    prep_w_kernel<<<(EE * DD * DD + 255) / 256, 256>>>(W_e);
    fused_kernel<<<BB * NN, 256>>>(nodes, edges, mask, b_e,
                                   gruK, gruR, gruB, out);
}